// round 14
// baseline (speedup 1.0000x reference)
#include <cuda_runtime.h>
#include <cstdint>

// LIF neuron scan: 2048 serial timesteps over 16384 independent neurons.
// R12: fully warp-private pipelines — ZERO __syncthreads.
//   Each warp owns 32 neurons and a private 7-slot x 8KB smem ring.
//   Each warp issues its own cp.async groups, waits its own wait_group,
//   computes its chain, stores via __stcs. Warps never synchronize, so no
//   warp pays for another warp's DRAM jitter (the lockstep tax of R8).
// Safety: refill of slot (c-1)%S is issued AFTER compute of chunk c; the
// last LDS of that slot (chunk c-1) was consumed >=1 compute chain + the
// cp.async's own DRAM latency before the overwrite lands.

#define LIF_T 2048
#define LIF_N 16384
#define CHUNK 32
#define STAGES 7
#define NCHUNK (LIF_T / CHUNK)            // 64
#define BN 128                             // threads (=neurons) per block
#define WN 32                              // neurons per warp
#define SLOT_FLOATS (2 * CHUNK * WN)       // 2048 floats = 8 KB per slot
#define WARP_FLOATS (STAGES * SLOT_FLOATS) // 14336 floats = 56 KB per warp
#define SMEM_BYTES (4 * WARP_FLOATS * 4)   // 224 KB

__device__ __forceinline__ void cp16(float* dst, const float4* src) {
    uint32_t s = (uint32_t)__cvta_generic_to_shared(dst);
    asm volatile("cp.async.cg.shared.global [%0], [%1], 16;\n"
                 :: "r"(s), "l"(src));
}
__device__ __forceinline__ void cp_commit() {
    asm volatile("cp.async.commit_group;\n" ::: "memory");
}
template <int N>
__device__ __forceinline__ void cp_wait() {
    asm volatile("cp.async.wait_group %0;\n" :: "n"(N) : "memory");
}

// One warp issues one stage: CHUNK rows x 32 neurons for I and Z.
// 512 float4 / 32 lanes = 16 cp.async per lane, one commit group.
// Layout per slot: sI = rows of 32 floats (128 B, conflict-free), sZ follows.
__device__ __forceinline__ void issue_stage_warp(
    float* __restrict__ wring, int c, int slot,
    const float4* __restrict__ gI4, const float4* __restrict__ gZ4,
    int lane)
{
    float* sI = wring + slot * SLOT_FLOATS;
    float* sZ = sI + CHUNK * WN;
#pragma unroll
    for (int k = 0; k < 16; ++k) {
        const int idx = k * 32 + lane;     // 0..511
        const int half = idx >> 8;         // 0 = I, 1 = Z
        const int sub = idx & 255;
        const int row = sub >> 3;          // 8 float4 per 32-neuron row
        const int col = sub & 7;
        const size_t goff = (size_t)(c * CHUNK + row) * (LIF_N / 4) + col;
        float* sdst = (half ? sZ : sI) + row * WN + col * 4;
        const float4* gsrc = (half ? gZ4 : gI4) + goff;
        cp16(sdst, gsrc);
    }
    cp_commit();
}

__global__ void __launch_bounds__(BN, 1)
TorchLIFNeuronGroup_kernel(const float* __restrict__ gI,
                           const float* __restrict__ gZ,
                           float* __restrict__ gOut)
{
    extern __shared__ float smem[];
    const int tid = threadIdx.x;
    const int w = tid >> 5;
    const int lane = tid & 31;
    float* wring = smem + w * WARP_FLOATS;

    // This warp's global slab: 32 neurons at blockN + w*32 (128 B, aligned).
    const int warpN = blockIdx.x * BN + w * WN;
    const float4* gI4 = (const float4*)(gI + warpN);
    const float4* gZ4 = (const float4*)(gZ + warpN);
    const int n = warpN + lane;

    // Prologue: fill slots 0..STAGES-2 (slot STAGES-1 is the reuse margin).
#pragma unroll
    for (int s = 0; s < STAGES - 1; ++s)
        issue_stage_warp(wring, s, s, gI4, gZ4, lane);

    float V = 0.0f;    // V_RESET
    float Vth = 1.0f;  // V_TH0

    for (int c = 0; c < NCHUNK; ++c) {
        const int slot = c % STAGES;

        // Need chunk c's group complete. Issued so far (this warp):
        // STAGES-1 + c groups; pending allowed = min(STAGES-2, NCHUNK-1-c).
        const int rem = (NCHUNK - 1 - c < STAGES - 2) ? (NCHUNK - 1 - c)
                                                      : (STAGES - 2);
        switch (rem) {
            case 5: cp_wait<5>(); break;
            case 4: cp_wait<4>(); break;
            case 3: cp_wait<3>(); break;
            case 2: cp_wait<2>(); break;
            case 1: cp_wait<1>(); break;
            default: cp_wait<0>(); break;
        }
        // No __syncthreads: slot data is warp-private; warp lockstep + the
        // register dependency chain give all needed ordering.

        // Compute CHUNK timesteps (bit-exact body); scattered coalesced stcs.
        {
            const float* sI = wring + slot * SLOT_FLOATS + lane;
            const float* sZ = sI + CHUNK * WN;
            float* pO = gOut + (size_t)c * CHUNK * LIF_N + n;
#pragma unroll
            for (int u = 0; u < CHUNK; ++u) {
                const float I  = sI[u * WN];
                const float nz = sZ[u * WN];
                // V = V + (DT/TAU)*(I - V) + noise  (reference op order)
                V = __fmaf_rn(0.05f, I - V, V) + nz;
                const bool sp = (V >= Vth);
                __stcs(pO + (size_t)u * LIF_N, sp ? 1.0f : 0.0f);
                V = sp ? 0.0f : V;
                // Vth starts at 1.0, never decreases -> lower clip is a no-op.
                Vth = sp ? Vth + 0.1f : Vth;
                Vth = fminf(Vth, 2.0f);
            }
        }

        // Refill AFTER compute: slot (c-1)%STAGES == (c+STAGES-1)%STAGES was
        // last read one full chunk ago; maximal safety margin vs in-flight LDS.
        if (c + STAGES - 1 < NCHUNK)
            issue_stage_warp(wring, c + STAGES - 1, (c + STAGES - 1) % STAGES,
                             gI4, gZ4, lane);
    }
}

extern "C" void kernel_launch(void* const* d_in, const int* in_sizes, int n_in,
                              void* d_out, int out_size)
{
    const float* input_current = (const float*)d_in[0];
    const float* noise         = (const float*)d_in[1];
    float* out                 = (float*)d_out;

    cudaFuncSetAttribute(TorchLIFNeuronGroup_kernel,
                         cudaFuncAttributeMaxDynamicSharedMemorySize, SMEM_BYTES);

    TorchLIFNeuronGroup_kernel<<<LIF_N / BN, BN, SMEM_BYTES>>>(
        input_current, noise, out);
}